// round 8
// baseline (speedup 1.0000x reference)
#include <cuda_runtime.h>
#include <cstdint>

#define T_STEPS 2048
#define BATCH 16
#define DIM 1024
#define NCTA 128
#define STEP_ELEMS (BATCH * DIM)                  // 16384
#define OUTS_ELEMS ((size_t)T_STEPS * STEP_ELEMS) // 33554432

// Grid-barrier counter (monotonic). Reset by init_kernel every launch/replay.
__device__ unsigned int g_cnt0;

__device__ __forceinline__ float my_tanh(float x) {
    float ax = fabsf(x);
    float e  = __expf(2.0f * ax);
    float r  = 1.0f - 2.0f / (e + 1.0f);
    return copysignf(r, x);
}
__device__ __forceinline__ float my_sigmoid(float x) {
    return 1.0f / (1.0f + __expf(-x));
}

__device__ __forceinline__ void cp_async16(uint32_t smem_addr, const void* gptr) {
    asm volatile("cp.async.cg.shared.global [%0], [%1], 16;\n"
                 :: "r"(smem_addr), "l"(gptr) : "memory");
}
__device__ __forceinline__ void cp_commit() {
    asm volatile("cp.async.commit_group;\n" ::: "memory");
}
#define CP_WAIT(n) asm volatile("cp.async.wait_group %0;\n" :: "n"(n) : "memory")

__device__ __forceinline__ void arrive_release(unsigned* p) {
    asm volatile("red.add.release.gpu.u32 [%0], %1;" :: "l"(p), "r"(1u) : "memory");
}
__device__ __forceinline__ unsigned ld_acquire(unsigned* p) {
    unsigned v;
    asm volatile("ld.acquire.gpu.u32 %0, [%1];" : "=r"(v) : "l"(p) : "memory");
    return v;
}
__device__ __forceinline__ void st_relaxed_gpu(float* p, float v) {
    asm volatile("st.relaxed.gpu.global.f32 [%0], %1;" :: "l"(p), "f"(v) : "memory");
}

// SW128 swizzle on byte offsets (16B granularity): folds bits [7:10) into [4:7).
__device__ __forceinline__ int swz128(int o) { return o ^ ((o >> 3) & 0x70); }

// ---------------------------------------------------------------------------
// Init: h0 -> hbuf slot 0; reset barrier counter.
// ---------------------------------------------------------------------------
__global__ void init_kernel(const float* __restrict__ h0, float* __restrict__ hbuf) {
    int i = blockIdx.x * blockDim.x + threadIdx.x;
    if (i < STEP_ELEMS) hbuf[i] = h0[i];
    if (i == 0) g_cnt0 = 0u;
}

// ---------------------------------------------------------------------------
// Fused persistent kernel. 128 CTAs x 256 threads; CTA owns 8 e-columns.
// Thread = (ep = tid&3 -> e-cols {2ep, 2ep+1}, c = tid>>2 -> k in [16c,16c+16)).
// h[t] and x[t+1] staged in smem with SW128 swizzle (stride-64B reads become
// conflict-free; 4 lanes sharing a k-chunk broadcast).
// Reduction: shfl_xor(4) merges chunk pairs, quarter-lanes store float2
// partials (permuted), 2 halves sum 16 partials each, combine via red_sh.
// ---------------------------------------------------------------------------
__global__ void __launch_bounds__(256, 1)
fused_kernel(const float* __restrict__ x,  const float* __restrict__ Wx,
             const float* __restrict__ Wh, const float* __restrict__ bias,
             const float* __restrict__ la, float* __restrict__ outs,
             float* __restrict__ hbuf) {
    extern __shared__ float sm[];
    float* h_sh   = sm;            // 16384 floats (64 KB), swizzled [b][1024]
    float* x_sh   = sm + 16384;    // 16384 floats (64 KB), swizzled
    float* part   = sm + 32768;    // 4096 floats (16 KB) = 2048 float2
    float* red_sh = sm + 36864;    // 128 floats
    float* wxr    = sm + 36992;    // 2 x 128 floats (wx ring)

    const int tid = threadIdx.x;
    const int ep  = tid & 3;               // e-pair id
    const int c   = tid >> 2;              // 0..63: k-chunk (16 k's)
    const int e0g = blockIdx.x * 8 + ep * 2;

    const float alpha = __expf(la[0]);

    // Register-resident weight slices: wh[e][q], wx[e][q] (e in {0,1}, q k-sub4).
    float4 whv[2][4], wxv[2][4];
#pragma unroll
    for (int e = 0; e < 2; e++)
#pragma unroll
        for (int q = 0; q < 4; q++) {
            whv[e][q] = *(const float4*)(Wh + (size_t)(e0g + e) * DIM + c * 16 + q * 4);
            wxv[e][q] = *(const float4*)(Wx + (size_t)(e0g + e) * DIM + c * 16 + q * 4);
        }

    // Precomputed swizzled in-row byte offsets for this thread's 4 sub-chunks.
    int swz[4];
#pragma unroll
    for (int q = 0; q < 4; q++) swz[q] = swz128(c * 64 + q * 16);

    const uint32_t h_u32 = (uint32_t)__cvta_generic_to_shared(h_sh);
    const uint32_t x_u32 = (uint32_t)__cvta_generic_to_shared(x_sh);

    // Finalize / reduction-read roles.
    const int out_id  = tid & 127;
    const int halfsel = tid >> 7;
    const int fb  = out_id >> 3;
    const int fe  = out_id & 7;
    const int eg  = blockIdx.x * 8 + fe;
    const int epr = fe >> 1;
    const int el  = fe & 1;
    const float bias_eg = bias[eg];
    // h_old smem address (swizzled) for (fb, eg).
    const char* hold_p = (const char*)h_sh + fb * 4096 + swz128(eg * 4 - blockIdx.x * 0)
                         ;
    // note: eg*4 < 4096 in-row offset; swz128 operates on bits <10 only.

// Issue the 16KB x tile for step xt into x_sh (swizzled). One commit group.
#define ISSUE_X(xt)                                                             \
    do {                                                                        \
        const float4* xs = (const float4*)(x + (size_t)(xt) * STEP_ELEMS);      \
        _Pragma("unroll")                                                       \
        for (int i = 0; i < 16; i++) {                                          \
            int u = i * 256 + tid;                                              \
            cp_async16(x_u32 + (uint32_t)swz128(u * 16), xs + u);               \
        }                                                                       \
        cp_commit();                                                            \
    } while (0)

// FMA over batches [B0, B0+NB) from tile at byte base SB into ACC[16][2].
#define DOT_RANGE(SB, W, ACC, B0, NB)                                           \
    do {                                                                        \
        _Pragma("unroll")                                                       \
        for (int bb = 0; bb < (NB); bb++) {                                     \
            const int b = (B0) + bb;                                            \
            const char* pb = (const char*)(SB) + b * 4096;                      \
            float4 v0 = *(const float4*)(pb + swz[0]);                          \
            float4 v1 = *(const float4*)(pb + swz[1]);                          \
            float4 v2 = *(const float4*)(pb + swz[2]);                          \
            float4 v3 = *(const float4*)(pb + swz[3]);                          \
            _Pragma("unroll")                                                   \
            for (int e = 0; e < 2; e++) {                                       \
                float a = ACC[b][e];                                            \
                a = fmaf(v0.x, W[e][0].x, a); a = fmaf(v0.y, W[e][0].y, a);     \
                a = fmaf(v0.z, W[e][0].z, a); a = fmaf(v0.w, W[e][0].w, a);     \
                a = fmaf(v1.x, W[e][1].x, a); a = fmaf(v1.y, W[e][1].y, a);     \
                a = fmaf(v1.z, W[e][1].z, a); a = fmaf(v1.w, W[e][1].w, a);     \
                a = fmaf(v2.x, W[e][2].x, a); a = fmaf(v2.y, W[e][2].y, a);     \
                a = fmaf(v2.z, W[e][2].z, a); a = fmaf(v2.w, W[e][2].w, a);     \
                a = fmaf(v3.x, W[e][3].x, a); a = fmaf(v3.y, W[e][3].y, a);     \
                a = fmaf(v3.z, W[e][3].z, a); a = fmaf(v3.w, W[e][3].w, a);     \
                ACC[b][e] = a;                                                  \
            }                                                                   \
        }                                                                       \
    } while (0)

// Reduce ACC[16][2] over the 64 k-chunks -> rsum (+ red_sh[out_id] pending).
#define REDUCE2H(ACC, rsum)                                                     \
    do {                                                                        \
        _Pragma("unroll")                                                       \
        for (int b = 0; b < 16; b++) {                                          \
            ACC[b][0] += __shfl_xor_sync(0xffffffffu, ACC[b][0], 4);            \
            ACC[b][1] += __shfl_xor_sync(0xffffffffu, ACC[b][1], 4);            \
        }                                                                       \
        if ((tid & 4) == 0) {                                                   \
            const int p = tid >> 3;                                             \
            _Pragma("unroll")                                                   \
            for (int b = 0; b < 16; b++) {                                      \
                int idx2 = p * 64 + ((b * 4 + ep + p * 4) & 63);                \
                ((float2*)part)[idx2] = make_float2(ACC[b][0], ACC[b][1]);      \
            }                                                                   \
        }                                                                       \
        __syncthreads();                                                        \
        {                                                                       \
            float s0 = 0.f, s1 = 0.f, s2 = 0.f, s3 = 0.f;                       \
            const int pb_ = halfsel * 16;                                       \
            _Pragma("unroll")                                                   \
            for (int u = 0; u < 16; u += 4) {                                   \
                int p0 = pb_ + u, p1 = p0 + 1, p2 = p0 + 2, p3 = p0 + 3;        \
                s0 += part[(p0 * 64 + ((fb * 4 + epr + p0 * 4) & 63)) * 2 + el];\
                s1 += part[(p1 * 64 + ((fb * 4 + epr + p1 * 4) & 63)) * 2 + el];\
                s2 += part[(p2 * 64 + ((fb * 4 + epr + p2 * 4) & 63)) * 2 + el];\
                s3 += part[(p3 * 64 + ((fb * 4 + epr + p3 * 4) & 63)) * 2 + el];\
            }                                                                   \
            rsum = (s0 + s1) + (s2 + s3);                                       \
        }                                                                       \
        if (halfsel) red_sh[out_id] = rsum;                                     \
        __syncthreads();                                                        \
    } while (0)

    // ---- Prologue: x[0] -> x_sh, compute wx[0] into ring slot 0.
    ISSUE_X(0);
    CP_WAIT(0);
    __syncthreads();
    {
        float accX[16][2];
#pragma unroll
        for (int b = 0; b < 16; b++) { accX[b][0] = 0.f; accX[b][1] = 0.f; }
        DOT_RANGE(x_sh, wxv, accX, 0, 16);
        float s;
        REDUCE2H(accX, s);
        if (halfsel == 0) wxr[out_id] = s + red_sh[out_id] + bias_eg;
        __syncthreads();
    }

    // ---- Main loop.
#pragma unroll 1
    for (int t = 0; t < T_STEPS; t++) {
        const size_t obase = (size_t)t * STEP_ELEMS;

        // All-thread acquire-poll: h[t] fully published (t=0 from init).
        if (t > 0) {
            const unsigned tgt = (unsigned)t * NCTA;
            while (ld_acquire(&g_cnt0) < tgt) { }
        }

        // Issue h[t] as 4 batch-quarter groups (16 KB each, swizzled).
        {
            const float4* src = (const float4*)(hbuf + obase);
#pragma unroll
            for (int g = 0; g < 4; g++) {
#pragma unroll
                for (int i = 0; i < 4; i++) {
                    int u = g * 1024 + i * 256 + tid;
                    cp_async16(h_u32 + (uint32_t)swz128(u * 16), src + u);
                }
                cp_commit();
            }
        }
        // Prefetch x[t+1] into x_sh (single buffer; consumed in this step's tail).
        {
            int xt = (t + 1 <= T_STEPS - 1) ? (t + 1) : (T_STEPS - 1);
            ISSUE_X(xt);
        }

        float accH[16][2];
#pragma unroll
        for (int b = 0; b < 16; b++) { accH[b][0] = 0.f; accH[b][1] = 0.f; }

        CP_WAIT(4); __syncthreads(); DOT_RANGE(h_sh, whv, accH, 0, 4);
        CP_WAIT(3); __syncthreads(); DOT_RANGE(h_sh, whv, accH, 4, 4);
        CP_WAIT(2); __syncthreads(); DOT_RANGE(h_sh, whv, accH, 8, 4);
        CP_WAIT(1); __syncthreads(); DOT_RANGE(h_sh, whv, accH, 12, 4);

        float hn = 0.0f;
        {
            float s;
            REDUCE2H(accH, s);
            if (halfsel == 0) {
                float pre  = s + red_sh[out_id] + wxr[(t & 1) * 128 + out_id];
                float hold = *(const float*)hold_p;
                hn = hold + alpha * my_tanh(pre);
                st_relaxed_gpu(&hbuf[(size_t)(t + 1) * STEP_ELEMS
                                     + (size_t)fb * DIM + eg], hn);
            }
        }
        __syncthreads();           // all h-slice stores issued before arrival

        if (tid == 0) arrive_release(&g_cnt0);

        // Off-critical-path: silu output store overlaps peers' polls.
        if (halfsel == 0) {
            float ot = hn * hn * my_sigmoid(hn);
            outs[obase + (size_t)fb * DIM + eg] = ot;
        }

        // GEMM tail: wx[t+1] from x_sh into ring slot (t+1)&1.
        CP_WAIT(0);
        if (t < T_STEPS - 1) {
            __syncthreads();
            float accX[16][2];
#pragma unroll
            for (int b = 0; b < 16; b++) { accX[b][0] = 0.f; accX[b][1] = 0.f; }
            DOT_RANGE(x_sh, wxv, accX, 0, 16);
            float s;
            REDUCE2H(accX, s);
            if (halfsel == 0)
                wxr[((t + 1) & 1) * 128 + out_id] = s + red_sh[out_id] + bias_eg;
        }
    }
#undef ISSUE_X
#undef DOT_RANGE
#undef REDUCE2H
}

// ---------------------------------------------------------------------------
// kernel_launch
//   inputs: x[T,B,D], h0[B,D], W_x[D,D], W_h[D,D], b[D], log_alpha[1]
//   output: [ outs (T*B*D) | h ((T+1)*B*D) ] float32
// ---------------------------------------------------------------------------
extern "C" void kernel_launch(void* const* d_in, const int* in_sizes, int n_in,
                              void* d_out, int out_size) {
    const float* x    = (const float*)d_in[0];
    const float* h0   = (const float*)d_in[1];
    const float* Wx   = (const float*)d_in[2];
    const float* Wh   = (const float*)d_in[3];
    const float* bias = (const float*)d_in[4];
    const float* la   = (const float*)d_in[5];

    float* outs = (float*)d_out;
    float* hbuf = outs + OUTS_ELEMS;

    const int smem_bytes = (16384 + 16384 + 4096 + 128 + 256) * sizeof(float);
    cudaFuncSetAttribute(fused_kernel, cudaFuncAttributeMaxDynamicSharedMemorySize,
                         smem_bytes);

    init_kernel<<<32, 512>>>(h0, hbuf);
    fused_kernel<<<NCTA, 256, smem_bytes>>>(x, Wx, Wh, bias, la, outs, hbuf);
}

// round 9
// speedup vs baseline: 1.1257x; 1.1257x over previous
#include <cuda_runtime.h>
#include <cstdint>

#define T_STEPS 2048
#define BATCH 16
#define DIM 1024
#define NCTA 128
#define STEP_ELEMS (BATCH * DIM)                  // 16384
#define OUTS_ELEMS ((size_t)T_STEPS * STEP_ELEMS) // 33554432

// Two independent half-recurrence counters (batches 0-7 / 8-15).
__device__ unsigned int g_cnt[2];

__device__ __forceinline__ float my_tanh(float x) {
    float ax = fabsf(x);
    float e  = __expf(2.0f * ax);
    float r  = 1.0f - 2.0f / (e + 1.0f);
    return copysignf(r, x);
}
__device__ __forceinline__ float my_sigmoid(float x) {
    return 1.0f / (1.0f + __expf(-x));
}

__device__ __forceinline__ void cp_async16(uint32_t smem_addr, const void* gptr) {
    asm volatile("cp.async.cg.shared.global [%0], [%1], 16;\n"
                 :: "r"(smem_addr), "l"(gptr) : "memory");
}
__device__ __forceinline__ void cp_commit() {
    asm volatile("cp.async.commit_group;\n" ::: "memory");
}
#define CP_WAIT(n) asm volatile("cp.async.wait_group %0;\n" :: "n"(n) : "memory")

// Named barrier: 128 threads of one warp-group.
#define GBAR(id) asm volatile("bar.sync %0, 128;" :: "r"(id) : "memory")

__device__ __forceinline__ void arrive_release(unsigned* p) {
    asm volatile("red.add.release.gpu.u32 [%0], %1;" :: "l"(p), "r"(1u) : "memory");
}
__device__ __forceinline__ unsigned ld_acquire(unsigned* p) {
    unsigned v;
    asm volatile("ld.acquire.gpu.u32 %0, [%1];" : "=r"(v) : "l"(p) : "memory");
    return v;
}
__device__ __forceinline__ void st_relaxed_gpu(float* p, float v) {
    asm volatile("st.relaxed.gpu.global.f32 [%0], %1;" :: "l"(p), "f"(v) : "memory");
}

// SW128 swizzle on byte offsets: folds bits [7:10) into [4:7).
__device__ __forceinline__ int swz128(int o) { return o ^ ((o >> 3) & 0x70); }

// ---------------------------------------------------------------------------
// Init: h0 -> hbuf slot 0; reset both counters.
// ---------------------------------------------------------------------------
__global__ void init_kernel(const float* __restrict__ h0, float* __restrict__ hbuf) {
    int i = blockIdx.x * blockDim.x + threadIdx.x;
    if (i < STEP_ELEMS) hbuf[i] = h0[i];
    if (i < 2) g_cnt[i] = 0u;
}

// ---------------------------------------------------------------------------
// Fused persistent kernel. 128 CTAs x 256 threads. CTA owns 8 e-columns.
// Warp-group wg = tid>>7 runs an INDEPENDENT half-recurrence over batches
// [8wg, 8wg+8): own smem buffers, own cp.async pipeline, own named barrier,
// own global counter. The two chains' sync windows overlap each other's
// compute on the shared SMSPs.
// Thread in group: ep = wtid&3 -> e-cols {2ep,2ep+1}; c = wtid>>2 -> k range
// [32c, 32c+32). Weights register-resident (64+64 floats).
// ---------------------------------------------------------------------------
__global__ void __launch_bounds__(256, 1)
fused_kernel(const float* __restrict__ x,  const float* __restrict__ Wx,
             const float* __restrict__ Wh, const float* __restrict__ bias,
             const float* __restrict__ la, float* __restrict__ outs,
             float* __restrict__ hbuf) {
    extern __shared__ float sm[];
    const int tid   = threadIdx.x;
    const int wg    = tid >> 7;            // 0 or 1: half-recurrence id
    const int wtid  = tid & 127;
    const int barid = 1 + wg;

    float* h_sh   = sm + wg * 8192;           // 8 x 1024 floats (32 KB)
    float* x_sh   = sm + 16384 + wg * 8192;   // 8 x 1024 floats (32 KB)
    float* part   = sm + 32768 + wg * 1024;   // 512 float2 (4 KB)
    float* red_sh = sm + 34816 + wg * 64;
    float* wxr    = sm + 34944 + wg * 128;    // 2 x 64 wx ring

    const int ep  = wtid & 3;
    const int c   = wtid >> 2;             // 0..31
    const int e0g = blockIdx.x * 8 + ep * 2;
    const int b0g = wg * 8;                // global batch base of this group

    const float alpha = __expf(la[0]);

    // Register-resident weight slices: 32 k's per e-column.
    float4 whv[2][8], wxv[2][8];
#pragma unroll
    for (int e = 0; e < 2; e++)
#pragma unroll
        for (int q = 0; q < 8; q++) {
            whv[e][q] = *(const float4*)(Wh + (size_t)(e0g + e) * DIM + c * 32 + q * 4);
            wxv[e][q] = *(const float4*)(Wx + (size_t)(e0g + e) * DIM + c * 32 + q * 4);
        }

    // Swizzled in-row byte offsets for this thread's 8 k-sub4 chunks.
    int swz[8];
#pragma unroll
    for (int q = 0; q < 8; q++) swz[q] = swz128(c * 128 + q * 16);

    const uint32_t h_u32 = (uint32_t)__cvta_generic_to_shared(h_sh);
    const uint32_t x_u32 = (uint32_t)__cvta_generic_to_shared(x_sh);

    // Finalize / reduction roles within the group (64 outputs: 8b x 8e).
    const int out_id  = wtid & 63;
    const int halfsel = wtid >> 6;
    const int fb  = out_id >> 3;           // local batch 0..7
    const int fe  = out_id & 7;
    const int eg  = blockIdx.x * 8 + fe;
    const int epr = fe >> 1;
    const int el  = fe & 1;
    const float bias_eg = bias[eg];
    const char* hold_p = (const char*)h_sh + fb * 4096 + swz128(eg * 4);

// Issue the 32KB x tile (8 batches of step xt) into x_sh. One commit group.
#define ISSUE_X(xt)                                                            \
    do {                                                                       \
        const float4* xs = (const float4*)(x + (size_t)(xt) * STEP_ELEMS       \
                                             + (size_t)b0g * DIM);             \
        _Pragma("unroll")                                                      \
        for (int i = 0; i < 16; i++) {                                         \
            int u = i * 128 + wtid;                                            \
            cp_async16(x_u32 + (uint32_t)swz128(u * 16), xs + u);              \
        }                                                                      \
        cp_commit();                                                           \
    } while (0)

// FMA over local batches [B0, B0+NB) from tile SB into ACC[8][2].
#define DOT_RANGE(SB, W, ACC, B0, NB)                                          \
    do {                                                                       \
        _Pragma("unroll")                                                      \
        for (int bb = 0; bb < (NB); bb++) {                                    \
            const int b = (B0) + bb;                                           \
            const char* pb = (const char*)(SB) + b * 4096;                     \
            _Pragma("unroll")                                                  \
            for (int q = 0; q < 8; q++) {                                      \
                float4 v = *(const float4*)(pb + swz[q]);                      \
                _Pragma("unroll")                                              \
                for (int e = 0; e < 2; e++) {                                  \
                    float a = ACC[b][e];                                       \
                    a = fmaf(v.x, W[e][q].x, a);                               \
                    a = fmaf(v.y, W[e][q].y, a);                               \
                    a = fmaf(v.z, W[e][q].z, a);                               \
                    a = fmaf(v.w, W[e][q].w, a);                               \
                    ACC[b][e] = a;                                             \
                }                                                              \
            }                                                                  \
        }                                                                      \
    } while (0)

// Reduce ACC[8][2] over 32 k-chunks -> rsum (pair with red_sh[out_id]).
#define REDUCE(ACC, rsum)                                                      \
    do {                                                                       \
        _Pragma("unroll")                                                      \
        for (int b = 0; b < 8; b++) {                                          \
            ACC[b][0] += __shfl_xor_sync(0xffffffffu, ACC[b][0], 4);           \
            ACC[b][1] += __shfl_xor_sync(0xffffffffu, ACC[b][1], 4);           \
        }                                                                      \
        if ((wtid & 4) == 0) {                                                 \
            const int p = wtid >> 3;                                           \
            _Pragma("unroll")                                                  \
            for (int b = 0; b < 8; b++) {                                      \
                int idx2 = (p * 8 + b) * 4 + ((ep + p) & 3);                   \
                ((float2*)part)[idx2] = make_float2(ACC[b][0], ACC[b][1]);     \
            }                                                                  \
        }                                                                      \
        GBAR(barid);                                                           \
        {                                                                      \
            float s0 = 0.f, s1 = 0.f;                                          \
            const int pb_ = halfsel * 8;                                       \
            _Pragma("unroll")                                                  \
            for (int u = 0; u < 8; u += 2) {                                   \
                int p0 = pb_ + u, p1 = p0 + 1;                                 \
                s0 += part[((p0 * 8 + fb) * 4 + ((epr + p0) & 3)) * 2 + el];   \
                s1 += part[((p1 * 8 + fb) * 4 + ((epr + p1) & 3)) * 2 + el];   \
            }                                                                  \
            rsum = s0 + s1;                                                    \
        }                                                                      \
        if (halfsel) red_sh[out_id] = rsum;                                    \
        GBAR(barid);                                                           \
    } while (0)

    // ---- Prologue: x[0] -> x_sh, wx[0] into ring slot 0.
    ISSUE_X(0);
    CP_WAIT(0);
    GBAR(barid);
    {
        float accX[8][2];
#pragma unroll
        for (int b = 0; b < 8; b++) { accX[b][0] = 0.f; accX[b][1] = 0.f; }
        DOT_RANGE(x_sh, wxv, accX, 0, 8);
        float s;
        REDUCE(accX, s);
        if (halfsel == 0) wxr[out_id] = s + red_sh[out_id] + bias_eg;
        GBAR(barid);
    }

    // ---- Main loop (independent per group).
#pragma unroll 1
    for (int t = 0; t < T_STEPS; t++) {
        const size_t obase = (size_t)t * STEP_ELEMS;

        // Acquire-poll: this half's h[t] fully published (t=0 from init).
        if (t > 0) {
            const unsigned tgt = (unsigned)t * NCTA;
            while (ld_acquire(&g_cnt[wg]) < tgt) { }
        }

        // Issue this half's h[t] (8 rows) as 4 groups of 2 rows (8 KB each).
        {
            const float4* src = (const float4*)(hbuf + obase + (size_t)b0g * DIM);
#pragma unroll
            for (int g = 0; g < 4; g++) {
#pragma unroll
                for (int i = 0; i < 4; i++) {
                    int u = g * 512 + i * 128 + wtid;
                    cp_async16(h_u32 + (uint32_t)swz128(u * 16), src + u);
                }
                cp_commit();
            }
        }
        // Prefetch x[t+1] (single buffer; consumed in this step's tail).
        {
            int xt = (t + 1 <= T_STEPS - 1) ? (t + 1) : (T_STEPS - 1);
            ISSUE_X(xt);
        }

        float accH[8][2];
#pragma unroll
        for (int b = 0; b < 8; b++) { accH[b][0] = 0.f; accH[b][1] = 0.f; }

        CP_WAIT(4); GBAR(barid); DOT_RANGE(h_sh, whv, accH, 0, 2);
        CP_WAIT(3); GBAR(barid); DOT_RANGE(h_sh, whv, accH, 2, 2);
        CP_WAIT(2); GBAR(barid); DOT_RANGE(h_sh, whv, accH, 4, 2);
        CP_WAIT(1); GBAR(barid); DOT_RANGE(h_sh, whv, accH, 6, 2);

        float hn = 0.0f;
        {
            float s;
            REDUCE(accH, s);
            if (halfsel == 0) {
                float pre  = s + red_sh[out_id] + wxr[(t & 1) * 64 + out_id];
                float hold = *(const float*)hold_p;
                hn = hold + alpha * my_tanh(pre);
                st_relaxed_gpu(&hbuf[(size_t)(t + 1) * STEP_ELEMS
                                     + (size_t)(b0g + fb) * DIM + eg], hn);
            }
        }
        GBAR(barid);               // h stores + hold reads complete group-wide

        if (wtid == 0) arrive_release(&g_cnt[wg]);

        // Off-critical-path: silu output store overlaps peers' polls.
        if (halfsel == 0) {
            float ot = hn * hn * my_sigmoid(hn);
            outs[obase + (size_t)(b0g + fb) * DIM + eg] = ot;
        }

        // GEMM tail: wx[t+1] into ring slot (t+1)&1.
        CP_WAIT(0);
        if (t < T_STEPS - 1) {
            GBAR(barid);
            float accX[8][2];
#pragma unroll
            for (int b = 0; b < 8; b++) { accX[b][0] = 0.f; accX[b][1] = 0.f; }
            DOT_RANGE(x_sh, wxv, accX, 0, 8);
            float s;
            REDUCE(accX, s);
            if (halfsel == 0)
                wxr[((t + 1) & 1) * 64 + out_id] = s + red_sh[out_id] + bias_eg;
        }
    }
#undef ISSUE_X
#undef DOT_RANGE
#undef REDUCE
}

// ---------------------------------------------------------------------------
// kernel_launch
//   inputs: x[T,B,D], h0[B,D], W_x[D,D], W_h[D,D], b[D], log_alpha[1]
//   output: [ outs (T*B*D) | h ((T+1)*B*D) ] float32
// ---------------------------------------------------------------------------
extern "C" void kernel_launch(void* const* d_in, const int* in_sizes, int n_in,
                              void* d_out, int out_size) {
    const float* x    = (const float*)d_in[0];
    const float* h0   = (const float*)d_in[1];
    const float* Wx   = (const float*)d_in[2];
    const float* Wh   = (const float*)d_in[3];
    const float* bias = (const float*)d_in[4];
    const float* la   = (const float*)d_in[5];

    float* outs = (float*)d_out;
    float* hbuf = outs + OUTS_ELEMS;

    const int smem_bytes = (16384 + 16384 + 2048 + 128 + 256) * sizeof(float);
    cudaFuncSetAttribute(fused_kernel, cudaFuncAttributeMaxDynamicSharedMemorySize,
                         smem_bytes);

    init_kernel<<<32, 512>>>(h0, hbuf);
    fused_kernel<<<NCTA, 256, smem_bytes>>>(x, Wx, Wh, bias, la, outs, hbuf);
}